// round 7
// baseline (speedup 1.0000x reference)
#include <cuda_runtime.h>
#include <cuda_bf16.h>
#include <math.h>
#include <stdint.h>

#define KD    512
#define KH    8
#define KDH   64
#define KHID  2730
#define KB    4
#define KNS   4096
#define KNT   512
#define SROWS (KB*KNS)
#define TROWS (KB*KNT)
#define KPAD  2752
#define NPAD  5504

typedef __nv_bfloat16 bf;
#define DEVB(n, s) __device__ __align__(16) bf n[s]
#define DEVF(n, s) __device__ __align__(16) float n[s]

// activations / intermediates
DEVB(LsQh,SROWS*KD); DEVB(LsQl,SROWS*KD);
DEVB(LtKVh,TROWS*KD);DEVB(LtKVl,TROWS*KD);
DEVB(LtQh,TROWS*KD); DEVB(LtQl,TROWS*KD);
DEVB(LsKVh,SROWS*KD);DEVB(LsKVl,SROWS*KD);
DEVB(Qsh,SROWS*KD);  DEVB(Qsl,SROWS*KD);
DEVB(Ksh,TROWS*KD);  DEVB(Ksl,TROWS*KD);
DEVB(VtSh,KB*KD*KNT);DEVB(VtSl,KB*KD*KNT);
DEVB(Qth,TROWS*KD);  DEVB(Qtl,TROWS*KD);
DEVB(Kth,SROWS*KD);  DEVB(Ktl,SROWS*KD);
DEVB(VtTh,KB*KD*KNS);DEVB(VtTl,KB*KD*KNS);
DEVF(Sc,(size_t)KB*KH*KNS*KNT);
DEVB(Pph,(size_t)KB*KH*KNS*KNT); DEVB(Ppl,(size_t)KB*KH*KNS*KNT);
DEVB(AtSh,SROWS*KD); DEVB(AtSl,SROWS*KD);
DEVB(AtTh,TROWS*KD); DEVB(AtTl,TROWS*KD);
DEVB(H1Sh,SROWS*KD); DEVB(H1Sl,SROWS*KD);
DEVB(H1Th,TROWS*KD); DEVB(H1Tl,TROWS*KD);
DEVF(SctxF,SROWS*KD);
DEVF(TctxF,TROWS*KD);
DEVF(TmeanF,KB*KD);
DEVB(Hmh,SROWS*2*KD); DEVB(Hml,SROWS*2*KD);
DEVB(Gth,(size_t)SROWS*KPAD); DEVB(Gtl,(size_t)SROWS*KPAD);
// weights
DEVB(WqkvSh,3*KD*KD); DEVB(WqkvSl,3*KD*KD);
DEVB(WqkvTh,3*KD*KD); DEVB(WqkvTl,3*KD*KD);
DEVB(WoSh,KD*KD); DEVB(WoSl,KD*KD);
DEVB(WpSh,KD*KD); DEVB(WpSl,KD*KD);
DEVB(WoTh,KD*KD); DEVB(WoTl,KD*KD);
DEVB(WpTh,KD*KD); DEVB(WpTl,KD*KD);
DEVB(Winh,NPAD*2*KD); DEVB(Winl,NPAD*2*KD);   // INTERLEAVED u/v rows
DEVB(Wouth,KD*KPAD);  DEVB(Woutl,KD*KPAD);
DEVF(BinP,NPAD);                               // interleaved bias

__device__ __forceinline__ void splitw(float x, bf* H, bf* L){
    bf h = __float2bfloat16(x); *H = h; *L = __float2bfloat16(x - __bfloat162float(h));
}
__device__ __forceinline__ void mma_bf(float* c, const uint32_t* a, const uint32_t* b){
    asm volatile("mma.sync.aligned.m16n8k16.row.col.f32.bf16.bf16.f32 "
        "{%0,%1,%2,%3}, {%4,%5,%6,%7}, {%8,%9}, {%0,%1,%2,%3};"
        : "+f"(c[0]),"+f"(c[1]),"+f"(c[2]),"+f"(c[3])
        : "r"(a[0]),"r"(a[1]),"r"(a[2]),"r"(a[3]), "r"(b[0]),"r"(b[1]));
}
__device__ __forceinline__ uint32_t cvsm(const void* p){
    uint32_t a; asm("{ .reg .u64 t; cvta.to.shared.u64 t, %1; cvt.u32.u64 %0, t; }":"=r"(a):"l"(p)); return a;
}
__device__ __forceinline__ void ldm_x4(uint32_t* r, uint32_t a){
    asm volatile("ldmatrix.sync.aligned.m8n8.x4.shared.b16 {%0,%1,%2,%3}, [%4];"
        : "=r"(r[0]),"=r"(r[1]),"=r"(r[2]),"=r"(r[3]) : "r"(a));
}
#define CPA(d, s) asm volatile("cp.async.cg.shared.global [%0], [%1], 16;"::"r"(d),"l"(s):"memory")
#define CPA_COMMIT() asm volatile("cp.async.commit_group;":::"memory")
#define CPA_WAIT1() asm volatile("cp.async.wait_group 1;":::"memory")
#define CPA_WAIT0() asm volatile("cp.async.wait_group 0;":::"memory")

// ---------------- reductions ----------------
__device__ __forceinline__ float brSum(float v){
    __shared__ float sh[33]; __syncthreads();
    int ln = threadIdx.x&31, w = threadIdx.x>>5;
    #pragma unroll
    for(int o=16;o;o>>=1) v += __shfl_xor_sync(~0u,v,o);
    if(!ln) sh[w]=v; __syncthreads();
    if(!w){ int nw=blockDim.x>>5; float r=(ln<nw)?sh[ln]:0.f;
        #pragma unroll
        for(int o=16;o;o>>=1) r += __shfl_xor_sync(~0u,r,o);
        if(!ln) sh[32]=r; }
    __syncthreads(); return sh[32];
}
__device__ __forceinline__ float brMax(float v){
    __shared__ float sh[33]; __syncthreads();
    int ln = threadIdx.x&31, w = threadIdx.x>>5;
    #pragma unroll
    for(int o=16;o;o>>=1) v = fmaxf(v,__shfl_xor_sync(~0u,v,o));
    if(!ln) sh[w]=v; __syncthreads();
    if(!w){ int nw=blockDim.x>>5; float r=(ln<nw)?sh[ln]:-1e30f;
        #pragma unroll
        for(int o=16;o;o>>=1) r = fmaxf(r,__shfl_xor_sync(~0u,r,o));
        if(!ln) sh[32]=r; }
    __syncthreads(); return sh[32];
}

// ---------------- elementwise kernels ----------------
__global__ void __launch_bounds__(128)
ln_k(const float* __restrict__ x, const float* __restrict__ g, const float* __restrict__ b,
     bf* __restrict__ yh, bf* __restrict__ yl)
{
    long row = blockIdx.x;
    const float* px = x + row*KD;
    bf *ph = yh + row*KD, *pl = yl + row*KD;
    int t = threadIdx.x;
    float v[4]; float s=0.f;
    #pragma unroll
    for(int i=0;i<4;i++){ v[i]=px[t+(i<<7)]; s+=v[i]; }
    s = brSum(s); float m = s*(1.f/KD);
    float q=0.f;
    #pragma unroll
    for(int i=0;i<4;i++){ float d=v[i]-m; q+=d*d; }
    q = brSum(q); float inv = rsqrtf(q*(1.f/KD)+1e-5f);
    #pragma unroll
    for(int i=0;i<4;i++){ int c=t+(i<<7); splitw((v[i]-m)*inv*g[c]+b[c], ph+c, pl+c); }
}

__global__ void __launch_bounds__(128)
mixln_k(const float* __restrict__ sc, const float* __restrict__ tm,
        const float* __restrict__ g, const float* __restrict__ b,
        bf* __restrict__ yh, bf* __restrict__ yl)
{
    int row = blockIdx.x, bb = row>>12;
    const float *ps = sc + (long)row*KD, *pm = tm + (long)bb*KD;
    bf *ph = yh + (long)row*2*KD, *pl = yl + (long)row*2*KD;
    int t = threadIdx.x;
    float v[8]; float s=0.f;
    #pragma unroll
    for(int i=0;i<8;i++){ int c=t+(i<<7); v[i]=(c<KD)?ps[c]:pm[c-KD]; s+=v[i]; }
    s = brSum(s); float m = s*(1.f/1024.f);
    float q=0.f;
    #pragma unroll
    for(int i=0;i<8;i++){ float d=v[i]-m; q+=d*d; }
    q = brSum(q); float inv = rsqrtf(q*(1.f/1024.f)+1e-5f);
    #pragma unroll
    for(int i=0;i<8;i++){ int c=t+(i<<7); splitw((v[i]-m)*inv*g[c]+b[c], ph+c, pl+c); }
}

template<int NV>
__global__ void __launch_bounds__(256)
sm_k(const float* __restrict__ S, bf* __restrict__ Ph, bf* __restrict__ Pl)
{
    long row = blockIdx.x;
    const int cols = NV*256;
    const float* p = S + row*(long)cols;
    bf *ph = Ph + row*(long)cols, *pl = Pl + row*(long)cols;
    int t = threadIdx.x;
    float v[NV]; float mx=-1e30f;
    #pragma unroll
    for(int i=0;i<NV;i++){ v[i]=p[t+(i<<8)]; mx=fmaxf(mx,v[i]); }
    mx = brMax(mx);
    float s=0.f;
    #pragma unroll
    for(int i=0;i<NV;i++){ v[i]=__expf(v[i]-mx); s+=v[i]; }
    s = brSum(s); float inv = 1.f/s;
    #pragma unroll
    for(int i=0;i<NV;i++){ int c=t+(i<<8); splitw(v[i]*inv, ph+c, pl+c); }
}

__global__ void tmean_k(const float* __restrict__ tc, float* __restrict__ o)
{
    int i = blockIdx.x*blockDim.x + threadIdx.x;
    if(i >= KB*KD) return;
    int bb=i>>9, dd=i&511;
    const float* p = tc + (long)bb*KNT*KD + dd;
    float s=0.f;
    for(int t=0;t<KNT;t++) s += p[t*KD];
    o[i] = s*(1.f/KNT);
}

__global__ void conv_k(const float* __restrict__ s, bf* __restrict__ dh, bf* __restrict__ dl,
                       int dR, int dC, int sR, int sC)
{
    long i = (long)blockIdx.x*blockDim.x + threadIdx.x;
    if(i >= (long)dR*dC) return;
    int r = (int)(i/dC), c = (int)(i - (long)r*dC);
    float v = (r<sR && c<sC) ? s[(long)r*sC + c] : 0.f;
    splitw(v, dh+i, dl+i);
}

// Win interleave: dst row 2c+half = src row half*KHID+c (zero pad past KHID)
__global__ void convin_k(const float* __restrict__ s, bf* __restrict__ dh, bf* __restrict__ dl)
{
    long i = (long)blockIdx.x*blockDim.x + threadIdx.x;
    if(i >= (long)NPAD*2*KD) return;
    int r = (int)(i/(2*KD)), c = (int)(i - (long)r*(2*KD));
    int pair = r>>1, half = r&1;
    float v = (pair < KHID) ? s[(long)(half*KHID+pair)*(2*KD) + c] : 0.f;
    splitw(v, dh+i, dl+i);
}
__global__ void padbin_k(const float* __restrict__ s, float* __restrict__ d)
{
    int i = blockIdx.x*blockDim.x + threadIdx.x;
    if(i >= NPAD) return;
    int pair = i>>1, half = i&1;
    d[i] = (pair < KHID) ? s[half*KHID + pair] : 0.f;
}

// ---------------- split-bf16 HMMA GEMM (NT), M-tile 256 ----------------
// C[m,n] = alpha*sum_k A[m,k]*B[n,k]. M%256==0, N%BN==0, K%32==0, lds%8==0.
// 256 threads, 8 warps 2(M:128 rows)x4(N:BN/4). smem rows 40 bf16 (80B).
// doGate: columns hold interleaved (u,v); write silu(u+bu)*(v+bv) to Ch/Cl
// at column gn/2 (ldc = N/2).
template<int BN>
__global__ void __launch_bounds__(256)
gemm_mma(const bf* __restrict__ Ah, const bf* __restrict__ Al,
         const bf* __restrict__ Bh, const bf* __restrict__ Bl,
         const float* __restrict__ bias, int biasMode, const float* __restrict__ Res,
         float* __restrict__ Cf, bf* __restrict__ Ch, bf* __restrict__ Cl, int doGate,
         int K, int lda, int ldb, int ldc,
         int Hn, long sAb, long sAh2, long sBb, long sBh2, long sCb, long sCh2,
         float alpha)
{
    extern __shared__ char smem[];
    const int tid = threadIdx.x, lane = tid&31, w = tid>>5;
    const int wm = w&1, wn = w>>1;
    const int gid = lane>>2, t4 = lane&3;
    constexpr int NT  = BN/32;            // n8 tiles per warp
    constexpr int BW  = BN/64;            // B 16B words per thread per split
    constexpr int ASZ = 20480;            // 256 rows * 80 B
    constexpr int BSZ = BN*80;
    constexpr int SS  = 2*ASZ + 2*BSZ;

    int z = blockIdx.z, zb = z/Hn, zh = z - zb*Hn;
    long coff = (long)zb*sCb + (long)zh*sCh2;
    Ah += (long)zb*sAb + (long)zh*sAh2; Al += (long)zb*sAb + (long)zh*sAh2;
    Bh += (long)zb*sBb + (long)zh*sBh2; Bl += (long)zb*sBb + (long)zh*sBh2;

    const int row0 = blockIdx.y << 8;
    const int col0 = blockIdx.x * BN;
    uint32_t sb = cvsm(smem);
    int nch = K >> 5;

    float cc[8][NT][4];
    #pragma unroll
    for(int i=0;i<8;i++)
        #pragma unroll
        for(int j=0;j<NT;j++)
            #pragma unroll
            for(int q=0;q<4;q++) cc[i][j][q]=0.f;

    auto issue = [&](int kc){
        uint32_t bufb = sb + (uint32_t)(kc&1)*SS;
        int k0 = kc<<5;
        #pragma unroll
        for(int i=0;i<4;i++){
            int wd = tid + (i<<8); int r = wd>>2, wi = wd&3;
            uint32_t so = bufb + (uint32_t)(r*80 + wi*16);
            long go = (long)(row0+r)*lda + k0 + (wi<<3);
            CPA(so,       Ah+go);
            CPA(so + ASZ, Al+go);
        }
        #pragma unroll
        for(int i=0;i<BW;i++){
            int wd = tid + (i<<8); int r = wd>>2, wi = wd&3;
            uint32_t so = bufb + 2*ASZ + (uint32_t)(r*80 + wi*16);
            long go = (long)(col0+r)*ldb + k0 + (wi<<3);
            CPA(so,       Bh+go);
            CPA(so + BSZ, Bl+go);
        }
        CPA_COMMIT();
    };

    issue(0);
    for(int kc=0; kc<nch; kc++){
        if(kc+1 < nch){ issue(kc+1); CPA_WAIT1(); }
        else          { CPA_WAIT0(); }
        __syncthreads();
        uint32_t bufb = sb + (uint32_t)(kc&1)*SS;
        #pragma unroll
        for(int ks=0; ks<2; ks++){
            uint32_t bh[NT][2], bl[NT][2];
            #pragma unroll
            for(int jp=0; jp<NT/2; jp++){
                int nr = wn*(BN/4) + jp*16 + (lane&7) + (((lane>>4)&1)<<3);
                uint32_t cb = (uint32_t)(((lane>>3)&1)<<4);
                uint32_t ad = bufb + 2*ASZ + (uint32_t)(nr*80) + (uint32_t)(ks*32) + cb;
                ldm_x4(&bh[2*jp][0], ad);
                ldm_x4(&bl[2*jp][0], ad + BSZ);
            }
            #pragma unroll
            for(int mt=0; mt<8; mt++){
                int ar = wm*128 + mt*16 + (lane&15);
                uint32_t cb = (uint32_t)(((lane>>4)&1)<<4);
                uint32_t ad = bufb + (uint32_t)(ar*80) + (uint32_t)(ks*32) + cb;
                uint32_t ah[4], al[4];
                ldm_x4(ah, ad);
                ldm_x4(al, ad + ASZ);
                #pragma unroll
                for(int j=0; j<NT; j++){
                    mma_bf(cc[mt][j], ah, bh[j]);
                    mma_bf(cc[mt][j], ah, bl[j]);
                    mma_bf(cc[mt][j], al, bh[j]);
                }
            }
        }
        __syncthreads();
    }

    // epilogue
    #pragma unroll
    for(int mt=0;mt<8;mt++){
        #pragma unroll
        for(int j=0;j<NT;j++){
            int gn = col0 + wn*(BN/4) + j*8 + t4*2;
            #pragma unroll
            for(int h=0;h<2;h++){
                int gm = row0 + wm*128 + mt*16 + gid + 8*h;
                float v0 = cc[mt][j][2*h+0]*alpha;
                float v1 = cc[mt][j][2*h+1]*alpha;
                if(biasMode==1){ v0 += bias[gn]; v1 += bias[gn+1]; }
                else if(biasMode==2){ float bb = bias[gm]; v0 += bb; v1 += bb; }
                if(doGate){
                    float g = (v0/(1.f+__expf(-v0)))*v1;
                    long cr = (long)gm*ldc + (gn>>1);
                    splitw(g, Ch+cr, Cl+cr);
                } else {
                    long cr = (long)gm*ldc + coff + gn;
                    if(Res){ float2 rr = *(const float2*)(Res+cr); v0 += rr.x; v1 += rr.y; }
                    if(Cf){ float2 o; o.x=v0; o.y=v1; *(float2*)(Cf+cr) = o; }
                    if(Ch){
                        __nv_bfloat162 hp, lp;
                        hp.x = __float2bfloat16(v0); hp.y = __float2bfloat16(v1);
                        lp.x = __float2bfloat16(v0 - __bfloat162float(hp.x));
                        lp.y = __float2bfloat16(v1 - __bfloat162float(hp.y));
                        *(__nv_bfloat162*)(Ch+cr) = hp;
                        *(__nv_bfloat162*)(Cl+cr) = lp;
                    }
                }
            }
        }
    }
}

// ---------------- host ----------------
static void ltc(const bf* Ah, const bf* Al, const bf* Bh, const bf* Bl,
                const float* bias, int bMode, const float* Res,
                float* Cf, bf* Ch, bf* Cl, int doGate,
                int M, int N, int K, int lda, int ldb, int ldc, int nTile,
                int Z, int Hn, long sAb, long sAh, long sBb, long sBh, long sCb, long sCh,
                float alpha)
{
    if(nTile == 128){
        int smem = 2*(2*20480 + 2*128*80);   // 122880 B
        cudaFuncSetAttribute(gemm_mma<128>, cudaFuncAttributeMaxDynamicSharedMemorySize, smem);
        dim3 g(N/128, M/256, Z);
        gemm_mma<128><<<g, 256, smem>>>(Ah,Al,Bh,Bl,bias,bMode,Res,Cf,Ch,Cl,doGate,
                                        K,lda,ldb,ldc,Hn,sAb,sAh,sBb,sBh,sCb,sCh,alpha);
    } else {
        int smem = 2*(2*20480 + 2*64*80);    // 102400 B
        cudaFuncSetAttribute(gemm_mma<64>, cudaFuncAttributeMaxDynamicSharedMemorySize, smem);
        dim3 g(N/64, M/256, Z);
        gemm_mma<64><<<g, 256, smem>>>(Ah,Al,Bh,Bl,bias,bMode,Res,Cf,Ch,Cl,doGate,
                                       K,lda,ldb,ldc,Hn,sAb,sAh,sBb,sBh,sCb,sCh,alpha);
    }
}
#define SYM(T,v,s) T* v; { void* p_; cudaGetSymbolAddress(&p_, s); v = (T*)p_; }

extern "C" void kernel_launch(void* const* d_in, const int* in_sizes, int n_in,
                              void* d_out, int out_size)
{
    (void)in_sizes; (void)n_in; (void)out_size;
    const float* spatial   = (const float*)d_in[0];
    const float* temporal  = (const float*)d_in[1];
    const float* sLqg=(const float*)d_in[2],  *sLqb=(const float*)d_in[3];
    const float* sLkg=(const float*)d_in[4],  *sLkb=(const float*)d_in[5];
    const float* sWqkv=(const float*)d_in[6], *sBqkv=(const float*)d_in[7];
    const float* sWo=(const float*)d_in[8],   *sBo=(const float*)d_in[9];
    const float* sWp=(const float*)d_in[10],  *sBp=(const float*)d_in[11];
    const float* tLqg=(const float*)d_in[12], *tLqb=(const float*)d_in[13];
    const float* tLkg=(const float*)d_in[14], *tLkb=(const float*)d_in[15];
    const float* tWqkv=(const float*)d_in[16],*tBqkv=(const float*)d_in[17];
    const float* tWo=(const float*)d_in[18],  *tBo=(const float*)d_in[19];
    const float* tWp=(const float*)d_in[20],  *tBp=(const float*)d_in[21];
    const float* mLg=(const float*)d_in[22],  *mLb=(const float*)d_in[23];
    const float* mWin=(const float*)d_in[24], *mBin=(const float*)d_in[25];
    const float* mWout=(const float*)d_in[26],*mBout=(const float*)d_in[27];
    float* out = (float*)d_out;

    SYM(bf,lsqh,LsQh) SYM(bf,lsql,LsQl) SYM(bf,ltkh,LtKVh) SYM(bf,ltkl,LtKVl)
    SYM(bf,ltqh,LtQh) SYM(bf,ltql,LtQl) SYM(bf,lskh,LsKVh) SYM(bf,lskl,LsKVl)
    SYM(bf,qsh,Qsh) SYM(bf,qsl,Qsl) SYM(bf,ksh,Ksh) SYM(bf,ksl,Ksl)
    SYM(bf,vsh,VtSh) SYM(bf,vsl,VtSl) SYM(bf,qth,Qth) SYM(bf,qtl,Qtl)
    SYM(bf,kth,Kth) SYM(bf,ktl,Ktl) SYM(bf,vth,VtTh) SYM(bf,vtl,VtTl)
    SYM(float,sc,Sc) SYM(bf,pph,Pph) SYM(bf,ppl,Ppl)
    SYM(bf,ash,AtSh) SYM(bf,asl,AtSl) SYM(bf,ath,AtTh) SYM(bf,atl,AtTl)
    SYM(bf,h1sh,H1Sh) SYM(bf,h1sl,H1Sl) SYM(bf,h1th,H1Th) SYM(bf,h1tl,H1Tl)
    SYM(float,sctx,SctxF) SYM(float,tctx,TctxF) SYM(float,tmn,TmeanF)
    SYM(bf,hmh,Hmh) SYM(bf,hml,Hml)
    SYM(bf,gth,Gth) SYM(bf,gtl,Gtl)
    SYM(bf,wqsh,WqkvSh) SYM(bf,wqsl,WqkvSl) SYM(bf,wqth,WqkvTh) SYM(bf,wqtl,WqkvTl)
    SYM(bf,wosh,WoSh) SYM(bf,wosl,WoSl) SYM(bf,wpsh,WpSh) SYM(bf,wpsl,WpSl)
    SYM(bf,woth,WoTh) SYM(bf,wotl,WoTl) SYM(bf,wpth,WpTh) SYM(bf,wptl,WpTl)
    SYM(bf,winh,Winh) SYM(bf,winl,Winl) SYM(bf,wouth,Wouth) SYM(bf,woutl,Woutl)
    SYM(float,binp,BinP)

    #define CV(src,dh,dl,dR,dC,sR,sC) conv_k<<<(int)(((long)(dR)*(dC)+255)/256),256>>>(src,dh,dl,dR,dC,sR,sC)
    CV(sWqkv,wqsh,wqsl,3*KD,KD,3*KD,KD);
    CV(tWqkv,wqth,wqtl,3*KD,KD,3*KD,KD);
    CV(sWo,wosh,wosl,KD,KD,KD,KD);   CV(sWp,wpsh,wpsl,KD,KD,KD,KD);
    CV(tWo,woth,wotl,KD,KD,KD,KD);   CV(tWp,wpth,wptl,KD,KD,KD,KD);
    convin_k<<<(int)(((long)NPAD*2*KD+255)/256),256>>>(mWin, winh, winl);
    CV(mWout,wouth,woutl,KD,KPAD,KD,KHID);
    padbin_k<<<(NPAD+255)/256,256>>>(mBin, binp);

    ln_k<<<SROWS,128>>>(spatial, sLqg,sLqb, lsqh,lsql);
    ln_k<<<TROWS,128>>>(temporal,sLkg,sLkb, ltkh,ltkl);
    ln_k<<<TROWS,128>>>(temporal,tLqg,tLqb, ltqh,ltql);
    ln_k<<<SROWS,128>>>(spatial, tLkg,tLkb, lskh,lskl);

    // projections
    ltc(lsqh,lsql, wqsh,wqsl, sBqkv,1,0, 0,qsh,qsl,0, SROWS,KD,KD, KD,KD,KD,128, 1,1,0,0,0,0,0,0, 1.f);
    ltc(ltkh,ltkl, wqsh+KD*KD,wqsl+KD*KD, sBqkv+KD,1,0, 0,ksh,ksl,0, TROWS,KD,KD, KD,KD,KD,128, 1,1,0,0,0,0,0,0, 1.f);
    ltc(wqsh+2*KD*KD,wqsl+2*KD*KD, ltkh,ltkl, sBqkv+2*KD,2,0, 0,vsh,vsl,0, KD,KNT,KD, KD,KD,KNT,128,
        KB,1, 0,0, (long)KNT*KD,0, (long)KD*KNT,0, 1.f);
    ltc(ltqh,ltql, wqth,wqtl, tBqkv,1,0, 0,qth,qtl,0, TROWS,KD,KD, KD,KD,KD,128, 1,1,0,0,0,0,0,0, 1.f);
    ltc(lskh,lskl, wqth+KD*KD,wqtl+KD*KD, tBqkv+KD,1,0, 0,kth,ktl,0, SROWS,KD,KD, KD,KD,KD,128, 1,1,0,0,0,0,0,0, 1.f);
    ltc(wqth+2*KD*KD,wqtl+2*KD*KD, lskh,lskl, tBqkv+2*KD,2,0, 0,vth,vtl,0, KD,KNS,KD, KD,KD,KNS,128,
        KB,1, 0,0, (long)KNS*KD,0, (long)KD*KNS,0, 1.f);

    // spatial attention
    ltc(qsh,qsl, ksh,ksl, 0,0,0, sc,0,0,0, KNS,KNT,KDH, KD,KD,KNT,128,
        KB*KH,KH, (long)KNS*KD,KDH, (long)KNT*KD,KDH, (long)KH*KNS*KNT,(long)KNS*KNT, 0.125f);
    sm_k<2><<<KB*KH*KNS,256>>>(sc, pph, ppl);
    ltc(pph,ppl, vsh,vsl, 0,0,0, 0,ash,asl,0, KNS,KDH,KNT, KNT,KNT,KD,64,
        KB*KH,KH, (long)KH*KNS*KNT,(long)KNS*KNT, (long)KD*KNT,(long)KDH*KNT, (long)KNS*KD,KDH, 1.f);
    ltc(ash,asl, wosh,wosl, sBo,1,0, 0,h1sh,h1sl,0, SROWS,KD,KD, KD,KD,KD,128, 1,1,0,0,0,0,0,0, 1.f);
    ltc(h1sh,h1sl, wpsh,wpsl, sBp,1,spatial, sctx,0,0,0, SROWS,KD,KD, KD,KD,KD,128, 1,1,0,0,0,0,0,0, 1.f);

    // temporal attention
    ltc(qth,qtl, kth,ktl, 0,0,0, sc,0,0,0, KNT,KNS,KDH, KD,KD,KNS,128,
        KB*KH,KH, (long)KNT*KD,KDH, (long)KNS*KD,KDH, (long)KH*KNT*KNS,(long)KNT*KNS, 0.125f);
    sm_k<16><<<KB*KH*KNT,256>>>(sc, pph, ppl);
    ltc(pph,ppl, vth,vtl, 0,0,0, 0,ath,atl,0, KNT,KDH,KNS, KNS,KNS,KD,64,
        KB*KH,KH, (long)KH*KNT*KNS,(long)KNT*KNS, (long)KD*KNS,(long)KDH*KNS, (long)KNT*KD,KDH, 1.f);
    ltc(ath,atl, woth,wotl, tBo,1,0, 0,h1th,h1tl,0, TROWS,KD,KD, KD,KD,KD,128, 1,1,0,0,0,0,0,0, 1.f);
    ltc(h1th,h1tl, wpth,wptl, tBp,1,temporal, tctx,0,0,0, TROWS,KD,KD, KD,KD,KD,128, 1,1,0,0,0,0,0,0, 1.f);

    // mix
    tmean_k<<<(KB*KD+127)/128,128>>>(tctx, tmn);
    mixln_k<<<SROWS,128>>>(sctx, tmn, mLg, mLb, hmh, hml);
    // fused Win + SiLU gate (interleaved u/v): writes gate hi/lo directly
    ltc(hmh,hml, winh,winl, binp,1,0, 0,gth,gtl,1, SROWS,NPAD,2*KD, 2*KD,2*KD,KPAD,128, 1,1,0,0,0,0,0,0, 1.f);
    ltc(gth,gtl, wouth,woutl, mBout,1,sctx, out,0,0,0, SROWS,KD,KPAD, KPAD,KPAD,KD,128, 1,1,0,0,0,0,0,0, 1.f);
}

// round 8
// speedup vs baseline: 1.1473x; 1.1473x over previous
#include <cuda_runtime.h>
#include <cuda_bf16.h>
#include <math.h>
#include <stdint.h>

#define KD    512
#define KH    8
#define KDH   64
#define KHID  2730
#define KB    4
#define KNS   4096
#define KNT   512
#define SROWS (KB*KNS)
#define TROWS (KB*KNT)
#define KPAD  2752
#define NPAD  5504

typedef __nv_bfloat16 bf;
#define DEVB(n, s) __device__ __align__(16) bf n[s]
#define DEVF(n, s) __device__ __align__(16) float n[s]

// activations / intermediates
DEVB(LsQh,SROWS*KD); DEVB(LsQl,SROWS*KD);
DEVB(LtKVh,TROWS*KD);DEVB(LtKVl,TROWS*KD);
DEVB(LtQh,TROWS*KD); DEVB(LtQl,TROWS*KD);
DEVB(LsKVh,SROWS*KD);DEVB(LsKVl,SROWS*KD);
DEVB(Qsh,SROWS*KD);  DEVB(Qsl,SROWS*KD);
DEVB(Ksh,TROWS*KD);  DEVB(Ksl,TROWS*KD);
DEVB(VtSh,KB*KD*KNT);DEVB(VtSl,KB*KD*KNT);
DEVB(Qth,TROWS*KD);  DEVB(Qtl,TROWS*KD);
DEVB(Kth,SROWS*KD);  DEVB(Ktl,SROWS*KD);
DEVB(VtTh,KB*KD*KNS);DEVB(VtTl,KB*KD*KNS);
DEVF(Sc,(size_t)KB*KH*KNS*KNT);
DEVB(Pph,(size_t)KB*KH*KNS*KNT); DEVB(Ppl,(size_t)KB*KH*KNS*KNT);
DEVB(AtSh,SROWS*KD); DEVB(AtSl,SROWS*KD);
DEVB(AtTh,TROWS*KD); DEVB(AtTl,TROWS*KD);
DEVB(H1Sh,SROWS*KD); DEVB(H1Sl,SROWS*KD);
DEVB(H1Th,TROWS*KD); DEVB(H1Tl,TROWS*KD);
DEVF(SctxF,SROWS*KD);
DEVF(TctxF,TROWS*KD);
DEVF(TmeanF,KB*KD);
DEVB(Hmh,SROWS*2*KD); DEVB(Hml,SROWS*2*KD);
DEVB(Gth,(size_t)SROWS*KPAD); DEVB(Gtl,(size_t)SROWS*KPAD);
// weights
DEVB(WqkvSh,3*KD*KD); DEVB(WqkvSl,3*KD*KD);
DEVB(WqkvTh,3*KD*KD); DEVB(WqkvTl,3*KD*KD);
DEVB(WoSh,KD*KD); DEVB(WoSl,KD*KD);
DEVB(WpSh,KD*KD); DEVB(WpSl,KD*KD);
DEVB(WoTh,KD*KD); DEVB(WoTl,KD*KD);
DEVB(WpTh,KD*KD); DEVB(WpTl,KD*KD);
DEVB(Winh,NPAD*2*KD); DEVB(Winl,NPAD*2*KD);   // INTERLEAVED u/v rows
DEVB(Wouth,KD*KPAD);  DEVB(Woutl,KD*KPAD);
DEVF(BinP,NPAD);                               // interleaved bias

__device__ __forceinline__ void splitw(float x, bf* H, bf* L){
    bf h = __float2bfloat16(x); *H = h; *L = __float2bfloat16(x - __bfloat162float(h));
}
__device__ __forceinline__ void mma_bf(float* c, const uint32_t* a, const uint32_t* b){
    asm volatile("mma.sync.aligned.m16n8k16.row.col.f32.bf16.bf16.f32 "
        "{%0,%1,%2,%3}, {%4,%5,%6,%7}, {%8,%9}, {%0,%1,%2,%3};"
        : "+f"(c[0]),"+f"(c[1]),"+f"(c[2]),"+f"(c[3])
        : "r"(a[0]),"r"(a[1]),"r"(a[2]),"r"(a[3]), "r"(b[0]),"r"(b[1]));
}
__device__ __forceinline__ uint32_t cvsm(const void* p){
    uint32_t a; asm("{ .reg .u64 t; cvta.to.shared.u64 t, %1; cvt.u32.u64 %0, t; }":"=r"(a):"l"(p)); return a;
}
__device__ __forceinline__ void ldm_x4(uint32_t* r, uint32_t a){
    asm volatile("ldmatrix.sync.aligned.m8n8.x4.shared.b16 {%0,%1,%2,%3}, [%4];"
        : "=r"(r[0]),"=r"(r[1]),"=r"(r[2]),"=r"(r[3]) : "r"(a));
}
#define CPA(d, s) asm volatile("cp.async.cg.shared.global [%0], [%1], 16;"::"r"(d),"l"(s):"memory")
#define CPA_COMMIT() asm volatile("cp.async.commit_group;":::"memory")
#define CPA_WAIT1() asm volatile("cp.async.wait_group 1;":::"memory")
#define CPA_WAIT0() asm volatile("cp.async.wait_group 0;":::"memory")

// ---------------- reductions ----------------
__device__ __forceinline__ float brSum(float v){
    __shared__ float sh[33]; __syncthreads();
    int ln = threadIdx.x&31, w = threadIdx.x>>5;
    #pragma unroll
    for(int o=16;o;o>>=1) v += __shfl_xor_sync(~0u,v,o);
    if(!ln) sh[w]=v; __syncthreads();
    if(!w){ int nw=blockDim.x>>5; float r=(ln<nw)?sh[ln]:0.f;
        #pragma unroll
        for(int o=16;o;o>>=1) r += __shfl_xor_sync(~0u,r,o);
        if(!ln) sh[32]=r; }
    __syncthreads(); return sh[32];
}
__device__ __forceinline__ float brMax(float v){
    __shared__ float sh[33]; __syncthreads();
    int ln = threadIdx.x&31, w = threadIdx.x>>5;
    #pragma unroll
    for(int o=16;o;o>>=1) v = fmaxf(v,__shfl_xor_sync(~0u,v,o));
    if(!ln) sh[w]=v; __syncthreads();
    if(!w){ int nw=blockDim.x>>5; float r=(ln<nw)?sh[ln]:-1e30f;
        #pragma unroll
        for(int o=16;o;o>>=1) r = fmaxf(r,__shfl_xor_sync(~0u,r,o));
        if(!ln) sh[32]=r; }
    __syncthreads(); return sh[32];
}

// ---------------- elementwise kernels ----------------
__global__ void __launch_bounds__(128)
ln_k(const float* __restrict__ x, const float* __restrict__ g, const float* __restrict__ b,
     bf* __restrict__ yh, bf* __restrict__ yl)
{
    long row = blockIdx.x;
    const float* px = x + row*KD;
    bf *ph = yh + row*KD, *pl = yl + row*KD;
    int t = threadIdx.x;
    float v[4]; float s=0.f;
    #pragma unroll
    for(int i=0;i<4;i++){ v[i]=px[t+(i<<7)]; s+=v[i]; }
    s = brSum(s); float m = s*(1.f/KD);
    float q=0.f;
    #pragma unroll
    for(int i=0;i<4;i++){ float d=v[i]-m; q+=d*d; }
    q = brSum(q); float inv = rsqrtf(q*(1.f/KD)+1e-5f);
    #pragma unroll
    for(int i=0;i<4;i++){ int c=t+(i<<7); splitw((v[i]-m)*inv*g[c]+b[c], ph+c, pl+c); }
}

__global__ void __launch_bounds__(128)
mixln_k(const float* __restrict__ sc, const float* __restrict__ tm,
        const float* __restrict__ g, const float* __restrict__ b,
        bf* __restrict__ yh, bf* __restrict__ yl)
{
    int row = blockIdx.x, bb = row>>12;
    const float *ps = sc + (long)row*KD, *pm = tm + (long)bb*KD;
    bf *ph = yh + (long)row*2*KD, *pl = yl + (long)row*2*KD;
    int t = threadIdx.x;
    float v[8]; float s=0.f;
    #pragma unroll
    for(int i=0;i<8;i++){ int c=t+(i<<7); v[i]=(c<KD)?ps[c]:pm[c-KD]; s+=v[i]; }
    s = brSum(s); float m = s*(1.f/1024.f);
    float q=0.f;
    #pragma unroll
    for(int i=0;i<8;i++){ float d=v[i]-m; q+=d*d; }
    q = brSum(q); float inv = rsqrtf(q*(1.f/1024.f)+1e-5f);
    #pragma unroll
    for(int i=0;i<8;i++){ int c=t+(i<<7); splitw((v[i]-m)*inv*g[c]+b[c], ph+c, pl+c); }
}

template<int NV>
__global__ void __launch_bounds__(256)
sm_k(const float* __restrict__ S, bf* __restrict__ Ph, bf* __restrict__ Pl)
{
    long row = blockIdx.x;
    const int cols = NV*256;
    const float* p = S + row*(long)cols;
    bf *ph = Ph + row*(long)cols, *pl = Pl + row*(long)cols;
    int t = threadIdx.x;
    float v[NV]; float mx=-1e30f;
    #pragma unroll
    for(int i=0;i<NV;i++){ v[i]=p[t+(i<<8)]; mx=fmaxf(mx,v[i]); }
    mx = brMax(mx);
    float s=0.f;
    #pragma unroll
    for(int i=0;i<NV;i++){ v[i]=__expf(v[i]-mx); s+=v[i]; }
    s = brSum(s); float inv = 1.f/s;
    #pragma unroll
    for(int i=0;i<NV;i++){ int c=t+(i<<8); splitw(v[i]*inv, ph+c, pl+c); }
}

__global__ void tmean_k(const float* __restrict__ tc, float* __restrict__ o)
{
    int i = blockIdx.x*blockDim.x + threadIdx.x;
    if(i >= KB*KD) return;
    int bb=i>>9, dd=i&511;
    const float* p = tc + (long)bb*KNT*KD + dd;
    float s=0.f;
    for(int t=0;t<KNT;t++) s += p[t*KD];
    o[i] = s*(1.f/KNT);
}

__global__ void conv_k(const float* __restrict__ s, bf* __restrict__ dh, bf* __restrict__ dl,
                       int dR, int dC, int sR, int sC)
{
    long i = (long)blockIdx.x*blockDim.x + threadIdx.x;
    if(i >= (long)dR*dC) return;
    int r = (int)(i/dC), c = (int)(i - (long)r*dC);
    float v = (r<sR && c<sC) ? s[(long)r*sC + c] : 0.f;
    splitw(v, dh+i, dl+i);
}

// Win interleave: dst row 2c+half = src row half*KHID+c (zero pad past KHID)
__global__ void convin_k(const float* __restrict__ s, bf* __restrict__ dh, bf* __restrict__ dl)
{
    long i = (long)blockIdx.x*blockDim.x + threadIdx.x;
    if(i >= (long)NPAD*2*KD) return;
    int r = (int)(i/(2*KD)), c = (int)(i - (long)r*(2*KD));
    int pair = r>>1, half = r&1;
    float v = (pair < KHID) ? s[(long)(half*KHID+pair)*(2*KD) + c] : 0.f;
    splitw(v, dh+i, dl+i);
}
__global__ void padbin_k(const float* __restrict__ s, float* __restrict__ d)
{
    int i = blockIdx.x*blockDim.x + threadIdx.x;
    if(i >= NPAD) return;
    int pair = i>>1, half = i&1;
    d[i] = (pair < KHID) ? s[half*KHID + pair] : 0.f;
}

// ---------------- split-bf16 HMMA GEMM (NT), ldmatrix + cp.async 2-stage ----
// C[m,n] = alpha*sum_k A[m,k]*B[n,k] (+bias)(+Res). M%128==0, N%BN==0, K%32==0.
// 256 threads, 8 warps 2(M)x4(N). smem rows padded to 40 bf16 (80B).
// doGate: columns hold interleaved (u,v); write silu(u)*v to Ch/Cl at col gn/2.
template<int BN>
__global__ void __launch_bounds__(256)
gemm_mma(const bf* __restrict__ Ah, const bf* __restrict__ Al,
         const bf* __restrict__ Bh, const bf* __restrict__ Bl,
         const float* __restrict__ bias, int biasMode, const float* __restrict__ Res,
         float* __restrict__ Cf, bf* __restrict__ Ch, bf* __restrict__ Cl, int doGate,
         int K, int lda, int ldb, int ldc,
         int Hn, long sAb, long sAh2, long sBb, long sBh2, long sCb, long sCh2,
         float alpha)
{
    extern __shared__ char smem[];
    const int tid = threadIdx.x, lane = tid&31, w = tid>>5;
    const int wm = w&1, wn = w>>1;
    const int gid = lane>>2, t4 = lane&3;
    constexpr int NT = BN/32;           // n8 tiles per warp
    constexpr int BW = BN/64;           // B 16B words per thread per split
    constexpr int SS = 20480 + BN*160;  // bytes per pipeline stage

    int z = blockIdx.z, zb = z/Hn, zh = z - zb*Hn;
    long coff = (long)zb*sCb + (long)zh*sCh2;
    Ah += (long)zb*sAb + (long)zh*sAh2; Al += (long)zb*sAb + (long)zh*sAh2;
    Bh += (long)zb*sBb + (long)zh*sBh2; Bl += (long)zb*sBb + (long)zh*sBh2;

    const int row0 = blockIdx.y << 7;
    const int col0 = blockIdx.x * BN;
    uint32_t sb = cvsm(smem);
    int nch = K >> 5;

    float cc[4][NT][4];
    #pragma unroll
    for(int i=0;i<4;i++)
        #pragma unroll
        for(int j=0;j<NT;j++)
            #pragma unroll
            for(int q=0;q<4;q++) cc[i][j][q]=0.f;

    auto issue = [&](int kc){
        uint32_t bufb = sb + (uint32_t)(kc&1)*SS;
        int k0 = kc<<5;
        #pragma unroll
        for(int i=0;i<2;i++){
            int wd = tid + (i<<8); int r = wd>>2, wi = wd&3;
            uint32_t so = bufb + (uint32_t)(r*80 + wi*16);
            long go = (long)(row0+r)*lda + k0 + (wi<<3);
            CPA(so,         Ah+go);
            CPA(so + 10240, Al+go);
        }
        #pragma unroll
        for(int i=0;i<BW;i++){
            int wd = tid + (i<<8); int r = wd>>2, wi = wd&3;
            uint32_t so = bufb + 20480u + (uint32_t)(r*80 + wi*16);
            long go = (long)(col0+r)*ldb + k0 + (wi<<3);
            CPA(so,           Bh+go);
            CPA(so + BN*80u,  Bl+go);
        }
        CPA_COMMIT();
    };

    issue(0);
    for(int kc=0; kc<nch; kc++){
        if(kc+1 < nch){ issue(kc+1); CPA_WAIT1(); }
        else          { CPA_WAIT0(); }
        __syncthreads();
        uint32_t bufb = sb + (uint32_t)(kc&1)*SS;
        #pragma unroll
        for(int ks=0; ks<2; ks++){
            uint32_t bh[NT][2], bl[NT][2];
            #pragma unroll
            for(int jp=0; jp<NT/2; jp++){
                int nr = wn*(BN/4) + jp*16 + (lane&7) + (((lane>>4)&1)<<3);
                uint32_t cb = (uint32_t)(((lane>>3)&1)<<4);
                uint32_t ad = bufb + 20480u + (uint32_t)(nr*80) + (uint32_t)(ks*32) + cb;
                ldm_x4(&bh[2*jp][0], ad);
                ldm_x4(&bl[2*jp][0], ad + BN*80u);
            }
            #pragma unroll
            for(int mt=0; mt<4; mt++){
                int ar = wm*64 + mt*16 + (lane&15);
                uint32_t cb = (uint32_t)(((lane>>4)&1)<<4);
                uint32_t ad = bufb + (uint32_t)(ar*80) + (uint32_t)(ks*32) + cb;
                uint32_t ah[4], al[4];
                ldm_x4(ah, ad);
                ldm_x4(al, ad + 10240u);
                #pragma unroll
                for(int j=0; j<NT; j++){
                    mma_bf(cc[mt][j], ah, bh[j]);
                    mma_bf(cc[mt][j], ah, bl[j]);
                    mma_bf(cc[mt][j], al, bh[j]);
                }
            }
        }
        __syncthreads();
    }

    // epilogue
    #pragma unroll
    for(int mt=0;mt<4;mt++){
        #pragma unroll
        for(int j=0;j<NT;j++){
            int gn = col0 + wn*(BN/4) + j*8 + t4*2;
            #pragma unroll
            for(int h=0;h<2;h++){
                int gm = row0 + wm*64 + mt*16 + gid + 8*h;
                float v0 = cc[mt][j][2*h+0]*alpha;
                float v1 = cc[mt][j][2*h+1]*alpha;
                if(biasMode==1){ v0 += bias[gn]; v1 += bias[gn+1]; }
                else if(biasMode==2){ float bb = bias[gm]; v0 += bb; v1 += bb; }
                if(doGate){
                    float g = (v0/(1.f+__expf(-v0)))*v1;
                    long cr = (long)gm*ldc + (gn>>1);
                    splitw(g, Ch+cr, Cl+cr);
                } else {
                    long cr = (long)gm*ldc + coff + gn;
                    if(Res){ float2 rr = *(const float2*)(Res+cr); v0 += rr.x; v1 += rr.y; }
                    if(Cf){ float2 o; o.x=v0; o.y=v1; *(float2*)(Cf+cr) = o; }
                    if(Ch){
                        __nv_bfloat162 hp, lp;
                        hp.x = __float2bfloat16(v0); hp.y = __float2bfloat16(v1);
                        lp.x = __float2bfloat16(v0 - __bfloat162float(hp.x));
                        lp.y = __float2bfloat16(v1 - __bfloat162float(hp.y));
                        *(__nv_bfloat162*)(Ch+cr) = hp;
                        *(__nv_bfloat162*)(Cl+cr) = lp;
                    }
                }
            }
        }
    }
}

// ---------------- host ----------------
static void ltc(const bf* Ah, const bf* Al, const bf* Bh, const bf* Bl,
                const float* bias, int bMode, const float* Res,
                float* Cf, bf* Ch, bf* Cl, int doGate,
                int M, int N, int K, int lda, int ldb, int ldc, int nTile,
                int Z, int Hn, long sAb, long sAh, long sBb, long sBh, long sCb, long sCh,
                float alpha)
{
    if(nTile == 128){
        int smem = 2*(20480 + 128*160);   // 81920 B
        cudaFuncSetAttribute(gemm_mma<128>, cudaFuncAttributeMaxDynamicSharedMemorySize, smem);
        dim3 g(N/128, M/128, Z);
        gemm_mma<128><<<g, 256, smem>>>(Ah,Al,Bh,Bl,bias,bMode,Res,Cf,Ch,Cl,doGate,
                                        K,lda,ldb,ldc,Hn,sAb,sAh,sBb,sBh,sCb,sCh,alpha);
    } else {
        int smem = 2*(20480 + 64*160);    // 61440 B
        cudaFuncSetAttribute(gemm_mma<64>, cudaFuncAttributeMaxDynamicSharedMemorySize, smem);
        dim3 g(N/64, M/128, Z);
        gemm_mma<64><<<g, 256, smem>>>(Ah,Al,Bh,Bl,bias,bMode,Res,Cf,Ch,Cl,doGate,
                                       K,lda,ldb,ldc,Hn,sAb,sAh,sBb,sBh,sCb,sCh,alpha);
    }
}
#define SYM(T,v,s) T* v; { void* p_; cudaGetSymbolAddress(&p_, s); v = (T*)p_; }

extern "C" void kernel_launch(void* const* d_in, const int* in_sizes, int n_in,
                              void* d_out, int out_size)
{
    (void)in_sizes; (void)n_in; (void)out_size;
    const float* spatial   = (const float*)d_in[0];
    const float* temporal  = (const float*)d_in[1];
    const float* sLqg=(const float*)d_in[2],  *sLqb=(const float*)d_in[3];
    const float* sLkg=(const float*)d_in[4],  *sLkb=(const float*)d_in[5];
    const float* sWqkv=(const float*)d_in[6], *sBqkv=(const float*)d_in[7];
    const float* sWo=(const float*)d_in[8],   *sBo=(const float*)d_in[9];
    const float* sWp=(const float*)d_in[10],  *sBp=(const float*)d_in[11];
    const float* tLqg=(const float*)d_in[12], *tLqb=(const float*)d_in[13];
    const float* tLkg=(const float*)d_in[14], *tLkb=(const float*)d_in[15];
    const float* tWqkv=(const float*)d_in[16],*tBqkv=(const float*)d_in[17];
    const float* tWo=(const float*)d_in[18],  *tBo=(const float*)d_in[19];
    const float* tWp=(const float*)d_in[20],  *tBp=(const float*)d_in[21];
    const float* mLg=(const float*)d_in[22],  *mLb=(const float*)d_in[23];
    const float* mWin=(const float*)d_in[24], *mBin=(const float*)d_in[25];
    const float* mWout=(const float*)d_in[26],*mBout=(const float*)d_in[27];
    float* out = (float*)d_out;

    SYM(bf,lsqh,LsQh) SYM(bf,lsql,LsQl) SYM(bf,ltkh,LtKVh) SYM(bf,ltkl,LtKVl)
    SYM(bf,ltqh,LtQh) SYM(bf,ltql,LtQl) SYM(bf,lskh,LsKVh) SYM(bf,lskl,LsKVl)
    SYM(bf,qsh,Qsh) SYM(bf,qsl,Qsl) SYM(bf,ksh,Ksh) SYM(bf,ksl,Ksl)
    SYM(bf,vsh,VtSh) SYM(bf,vsl,VtSl) SYM(bf,qth,Qth) SYM(bf,qtl,Qtl)
    SYM(bf,kth,Kth) SYM(bf,ktl,Ktl) SYM(bf,vth,VtTh) SYM(bf,vtl,VtTl)
    SYM(float,sc,Sc) SYM(bf,pph,Pph) SYM(bf,ppl,Ppl)
    SYM(bf,ash,AtSh) SYM(bf,asl,AtSl) SYM(bf,ath,AtTh) SYM(bf,atl,AtTl)
    SYM(bf,h1sh,H1Sh) SYM(bf,h1sl,H1Sl) SYM(bf,h1th,H1Th) SYM(bf,h1tl,H1Tl)
    SYM(float,sctx,SctxF) SYM(float,tctx,TctxF) SYM(float,tmn,TmeanF)
    SYM(bf,hmh,Hmh) SYM(bf,hml,Hml)
    SYM(bf,gth,Gth) SYM(bf,gtl,Gtl)
    SYM(bf,wqsh,WqkvSh) SYM(bf,wqsl,WqkvSl) SYM(bf,wqth,WqkvTh) SYM(bf,wqtl,WqkvTl)
    SYM(bf,wosh,WoSh) SYM(bf,wosl,WoSl) SYM(bf,wpsh,WpSh) SYM(bf,wpsl,WpSl)
    SYM(bf,woth,WoTh) SYM(bf,wotl,WoTl) SYM(bf,wpth,WpTh) SYM(bf,wptl,WpTl)
    SYM(bf,winh,Winh) SYM(bf,winl,Winl) SYM(bf,wouth,Wouth) SYM(bf,woutl,Woutl)
    SYM(float,binp,BinP)

    #define CV(src,dh,dl,dR,dC,sR,sC) conv_k<<<(int)(((long)(dR)*(dC)+255)/256),256>>>(src,dh,dl,dR,dC,sR,sC)
    CV(sWqkv,wqsh,wqsl,3*KD,KD,3*KD,KD);
    CV(tWqkv,wqth,wqtl,3*KD,KD,3*KD,KD);
    CV(sWo,wosh,wosl,KD,KD,KD,KD);   CV(sWp,wpsh,wpsl,KD,KD,KD,KD);
    CV(tWo,woth,wotl,KD,KD,KD,KD);   CV(tWp,wpth,wptl,KD,KD,KD,KD);
    convin_k<<<(int)(((long)NPAD*2*KD+255)/256),256>>>(mWin, winh, winl);
    CV(mWout,wouth,woutl,KD,KPAD,KD,KHID);
    padbin_k<<<(NPAD+255)/256,256>>>(mBin, binp);

    ln_k<<<SROWS,128>>>(spatial, sLqg,sLqb, lsqh,lsql);
    ln_k<<<TROWS,128>>>(temporal,sLkg,sLkb, ltkh,ltkl);
    ln_k<<<TROWS,128>>>(temporal,tLqg,tLqb, ltqh,ltql);
    ln_k<<<SROWS,128>>>(spatial, tLkg,tLkb, lskh,lskl);

    // projections
    ltc(lsqh,lsql, wqsh,wqsl, sBqkv,1,0, 0,qsh,qsl,0, SROWS,KD,KD, KD,KD,KD,128, 1,1,0,0,0,0,0,0, 1.f);
    ltc(ltkh,ltkl, wqsh+KD*KD,wqsl+KD*KD, sBqkv+KD,1,0, 0,ksh,ksl,0, TROWS,KD,KD, KD,KD,KD,128, 1,1,0,0,0,0,0,0, 1.f);
    ltc(wqsh+2*KD*KD,wqsl+2*KD*KD, ltkh,ltkl, sBqkv+2*KD,2,0, 0,vsh,vsl,0, KD,KNT,KD, KD,KD,KNT,128,
        KB,1, 0,0, (long)KNT*KD,0, (long)KD*KNT,0, 1.f);
    ltc(ltqh,ltql, wqth,wqtl, tBqkv,1,0, 0,qth,qtl,0, TROWS,KD,KD, KD,KD,KD,128, 1,1,0,0,0,0,0,0, 1.f);
    ltc(lskh,lskl, wqth+KD*KD,wqtl+KD*KD, tBqkv+KD,1,0, 0,kth,ktl,0, SROWS,KD,KD, KD,KD,KD,128, 1,1,0,0,0,0,0,0, 1.f);
    ltc(wqth+2*KD*KD,wqtl+2*KD*KD, lskh,lskl, tBqkv+2*KD,2,0, 0,vth,vtl,0, KD,KNS,KD, KD,KD,KNS,128,
        KB,1, 0,0, (long)KNS*KD,0, (long)KD*KNS,0, 1.f);

    // spatial attention
    ltc(qsh,qsl, ksh,ksl, 0,0,0, sc,0,0,0, KNS,KNT,KDH, KD,KD,KNT,128,
        KB*KH,KH, (long)KNS*KD,KDH, (long)KNT*KD,KDH, (long)KH*KNS*KNT,(long)KNS*KNT, 0.125f);
    sm_k<2><<<KB*KH*KNS,256>>>(sc, pph, ppl);
    ltc(pph,ppl, vsh,vsl, 0,0,0, 0,ash,asl,0, KNS,KDH,KNT, KNT,KNT,KD,64,
        KB*KH,KH, (long)KH*KNS*KNT,(long)KNS*KNT, (long)KD*KNT,(long)KDH*KNT, (long)KNS*KD,KDH, 1.f);
    ltc(ash,asl, wosh,wosl, sBo,1,0, 0,h1sh,h1sl,0, SROWS,KD,KD, KD,KD,KD,128, 1,1,0,0,0,0,0,0, 1.f);
    ltc(h1sh,h1sl, wpsh,wpsl, sBp,1,spatial, sctx,0,0,0, SROWS,KD,KD, KD,KD,KD,128, 1,1,0,0,0,0,0,0, 1.f);

    // temporal attention
    ltc(qth,qtl, kth,ktl, 0,0,0, sc,0,0,0, KNT,KNS,KDH, KD,KD,KNS,128,
        KB*KH,KH, (long)KNT*KD,KDH, (long)KNS*KD,KDH, (long)KH*KNT*KNS,(long)KNT*KNS, 0.125f);
    sm_k<16><<<KB*KH*KNT,256>>>(sc, pph, ppl);
    ltc(pph,ppl, vth,vtl, 0,0,0, 0,ath,atl,0, KNT,KDH,KNS, KNS,KNS,KD,64,
        KB*KH,KH, (long)KH*KNT*KNS,(long)KNT*KNS, (long)KD*KNS,(long)KDH*KNS, (long)KNT*KD,KDH, 1.f);
    ltc(ath,atl, woth,wotl, tBo,1,0, 0,h1th,h1tl,0, TROWS,KD,KD, KD,KD,KD,128, 1,1,0,0,0,0,0,0, 1.f);
    ltc(h1th,h1tl, wpth,wptl, tBp,1,temporal, tctx,0,0,0, TROWS,KD,KD, KD,KD,KD,128, 1,1,0,0,0,0,0,0, 1.f);

    // mix
    tmean_k<<<(KB*KD+127)/128,128>>>(tctx, tmn);
    mixln_k<<<SROWS,128>>>(sctx, tmn, mLg, mLb, hmh, hml);
    // fused Win + SiLU gate (interleaved u/v): writes gate hi/lo directly
    ltc(hmh,hml, winh,winl, binp,1,0, 0,gth,gtl,1, SROWS,NPAD,2*KD, 2*KD,2*KD,KPAD,128, 1,1,0,0,0,0,0,0, 1.f);
    ltc(gth,gtl, wouth,woutl, mBout,1,sctx, out,0,0,0, SROWS,KD,KPAD, KPAD,KPAD,KD,128, 1,1,0,0,0,0,0,0, 1.f);
}

// round 9
// speedup vs baseline: 1.2370x; 1.0782x over previous
#include <cuda_runtime.h>
#include <cuda_bf16.h>
#include <math.h>
#include <stdint.h>

#define KD    512
#define KH    8
#define KDH   64
#define KHID  2730
#define KB    4
#define KNS   4096
#define KNT   512
#define SROWS (KB*KNS)
#define TROWS (KB*KNT)
#define KPAD  2752
#define NPAD  5504

typedef __nv_bfloat16 bf;
#define DEVB(n, s) __device__ __align__(16) bf n[s]
#define DEVF(n, s) __device__ __align__(16) float n[s]

DEVB(LsQh,SROWS*KD); DEVB(LsQl,SROWS*KD);
DEVB(LtKVh,TROWS*KD);DEVB(LtKVl,TROWS*KD);
DEVB(LtQh,TROWS*KD); DEVB(LtQl,TROWS*KD);
DEVB(LsKVh,SROWS*KD);DEVB(LsKVl,SROWS*KD);
DEVB(Qsh,SROWS*KD);  DEVB(Qsl,SROWS*KD);
DEVB(Ksh,TROWS*KD);  DEVB(Ksl,TROWS*KD);
DEVB(VtSh,KB*KD*KNT);DEVB(VtSl,KB*KD*KNT);
DEVB(Qth,TROWS*KD);  DEVB(Qtl,TROWS*KD);
DEVB(Kth,SROWS*KD);  DEVB(Ktl,SROWS*KD);
DEVB(VtTh,KB*KD*KNS);DEVB(VtTl,KB*KD*KNS);
DEVB(AtSh,SROWS*KD); DEVB(AtSl,SROWS*KD);
DEVB(AtTh,TROWS*KD); DEVB(AtTl,TROWS*KD);
DEVB(H1Sh,SROWS*KD); DEVB(H1Sl,SROWS*KD);
DEVB(H1Th,TROWS*KD); DEVB(H1Tl,TROWS*KD);
DEVF(SctxF,SROWS*KD);
DEVF(TctxF,TROWS*KD);
DEVF(TmeanF,KB*KD);
DEVB(Hmh,SROWS*2*KD); DEVB(Hml,SROWS*2*KD);
DEVB(Gth,(size_t)SROWS*KPAD); DEVB(Gtl,(size_t)SROWS*KPAD);
DEVB(WqkvSh,3*KD*KD); DEVB(WqkvSl,3*KD*KD);
DEVB(WqkvTh,3*KD*KD); DEVB(WqkvTl,3*KD*KD);
DEVB(WoSh,KD*KD); DEVB(WoSl,KD*KD);
DEVB(WpSh,KD*KD); DEVB(WpSl,KD*KD);
DEVB(WoTh,KD*KD); DEVB(WoTl,KD*KD);
DEVB(WpTh,KD*KD); DEVB(WpTl,KD*KD);
DEVB(Winh,NPAD*2*KD); DEVB(Winl,NPAD*2*KD);
DEVB(Wouth,KD*KPAD);  DEVB(Woutl,KD*KPAD);
DEVF(BinP,NPAD);

__device__ __forceinline__ void splitw(float x, bf* H, bf* L){
    bf h = __float2bfloat16(x); *H = h; *L = __float2bfloat16(x - __bfloat162float(h));
}
__device__ __forceinline__ void mma_bf(float* c, const uint32_t* a, const uint32_t* b){
    asm volatile("mma.sync.aligned.m16n8k16.row.col.f32.bf16.bf16.f32 "
        "{%0,%1,%2,%3}, {%4,%5,%6,%7}, {%8,%9}, {%0,%1,%2,%3};"
        : "+f"(c[0]),"+f"(c[1]),"+f"(c[2]),"+f"(c[3])
        : "r"(a[0]),"r"(a[1]),"r"(a[2]),"r"(a[3]), "r"(b[0]),"r"(b[1]));
}
__device__ __forceinline__ uint32_t cvsm(const void* p){
    uint32_t a; asm("{ .reg .u64 t; cvta.to.shared.u64 t, %1; cvt.u32.u64 %0, t; }":"=r"(a):"l"(p)); return a;
}
__device__ __forceinline__ void ldm_x4(uint32_t* r, uint32_t a){
    asm volatile("ldmatrix.sync.aligned.m8n8.x4.shared.b16 {%0,%1,%2,%3}, [%4];"
        : "=r"(r[0]),"=r"(r[1]),"=r"(r[2]),"=r"(r[3]) : "r"(a));
}
#define CPA(d, s) asm volatile("cp.async.cg.shared.global [%0], [%1], 16;"::"r"(d),"l"(s):"memory")
#define CPA_COMMIT() asm volatile("cp.async.commit_group;":::"memory")
#define CPA_WAIT1() asm volatile("cp.async.wait_group 1;":::"memory")
#define CPA_WAIT0() asm volatile("cp.async.wait_group 0;":::"memory")

__device__ __forceinline__ float brSum(float v){
    __shared__ float sh[33]; __syncthreads();
    int ln = threadIdx.x&31, w = threadIdx.x>>5;
    #pragma unroll
    for(int o=16;o;o>>=1) v += __shfl_xor_sync(~0u,v,o);
    if(!ln) sh[w]=v; __syncthreads();
    if(!w){ int nw=blockDim.x>>5; float r=(ln<nw)?sh[ln]:0.f;
        #pragma unroll
        for(int o=16;o;o>>=1) r += __shfl_xor_sync(~0u,r,o);
        if(!ln) sh[32]=r; }
    __syncthreads(); return sh[32];
}

// ---------------- elementwise ----------------
__global__ void __launch_bounds__(128)
ln_k(const float* __restrict__ x, const float* __restrict__ g, const float* __restrict__ b,
     bf* __restrict__ yh, bf* __restrict__ yl)
{
    long row = blockIdx.x;
    const float* px = x + row*KD;
    bf *ph = yh + row*KD, *pl = yl + row*KD;
    int t = threadIdx.x;
    float v[4]; float s=0.f;
    #pragma unroll
    for(int i=0;i<4;i++){ v[i]=px[t+(i<<7)]; s+=v[i]; }
    s = brSum(s); float m = s*(1.f/KD);
    float q=0.f;
    #pragma unroll
    for(int i=0;i<4;i++){ float d=v[i]-m; q+=d*d; }
    q = brSum(q); float inv = rsqrtf(q*(1.f/KD)+1e-5f);
    #pragma unroll
    for(int i=0;i<4;i++){ int c=t+(i<<7); splitw((v[i]-m)*inv*g[c]+b[c], ph+c, pl+c); }
}

__global__ void __launch_bounds__(128)
mixln_k(const float* __restrict__ sc, const float* __restrict__ tm,
        const float* __restrict__ g, const float* __restrict__ b,
        bf* __restrict__ yh, bf* __restrict__ yl)
{
    int row = blockIdx.x, bb = row>>12;
    const float *ps = sc + (long)row*KD, *pm = tm + (long)bb*KD;
    bf *ph = yh + (long)row*2*KD, *pl = yl + (long)row*2*KD;
    int t = threadIdx.x;
    float v[8]; float s=0.f;
    #pragma unroll
    for(int i=0;i<8;i++){ int c=t+(i<<7); v[i]=(c<KD)?ps[c]:pm[c-KD]; s+=v[i]; }
    s = brSum(s); float m = s*(1.f/1024.f);
    float q=0.f;
    #pragma unroll
    for(int i=0;i<8;i++){ float d=v[i]-m; q+=d*d; }
    q = brSum(q); float inv = rsqrtf(q*(1.f/1024.f)+1e-5f);
    #pragma unroll
    for(int i=0;i<8;i++){ int c=t+(i<<7); splitw((v[i]-m)*inv*g[c]+b[c], ph+c, pl+c); }
}

__global__ void tmean_k(const float* __restrict__ tc, float* __restrict__ o)
{
    int i = blockIdx.x*blockDim.x + threadIdx.x;
    if(i >= KB*KD) return;
    int bb=i>>9, dd=i&511;
    const float* p = tc + (long)bb*KNT*KD + dd;
    float s=0.f;
    for(int t=0;t<KNT;t++) s += p[t*KD];
    o[i] = s*(1.f/KNT);
}

__global__ void conv_k(const float* __restrict__ s, bf* __restrict__ dh, bf* __restrict__ dl,
                       int dR, int dC, int sR, int sC)
{
    long i = (long)blockIdx.x*blockDim.x + threadIdx.x;
    if(i >= (long)dR*dC) return;
    int r = (int)(i/dC), c = (int)(i - (long)r*dC);
    float v = (r<sR && c<sC) ? s[(long)r*sC + c] : 0.f;
    splitw(v, dh+i, dl+i);
}

__global__ void convin_k(const float* __restrict__ s, bf* __restrict__ dh, bf* __restrict__ dl)
{
    long i = (long)blockIdx.x*blockDim.x + threadIdx.x;
    if(i >= (long)NPAD*2*KD) return;
    int r = (int)(i/(2*KD)), c = (int)(i - (long)r*(2*KD));
    int pair = r>>1, half = r&1;
    float v = (pair < KHID) ? s[(long)(half*KHID+pair)*(2*KD) + c] : 0.f;
    splitw(v, dh+i, dl+i);
}
__global__ void padbin_k(const float* __restrict__ s, float* __restrict__ d)
{
    int i = blockIdx.x*blockDim.x + threadIdx.x;
    if(i >= NPAD) return;
    int pair = i>>1, half = i&1;
    d[i] = (pair < KHID) ? s[half*KHID + pair] : 0.f;
}

// ---------------- fused flash attention (split-bf16 HMMA) ----------------
// Per CTA: 128 q rows of one (b,h). K-blocks of 128 keys. K double-buffered.
// smem layout (bytes): Q hi 0 / lo 18432 (stride 144); K buf b at 36864+b*36864;
// V hi 110592 / lo +17408 (stride 272); U(S|P) 145408 stride 560 (S fp32 [0,512),
// P hi [0,256) lo [256,512) overwrite-after-read); rowscale 217088; rowlinv 217600.
__global__ void __launch_bounds__(256)
flash_k(const bf* __restrict__ Qh, const bf* __restrict__ Ql,
        const bf* __restrict__ Kh, const bf* __restrict__ Kl,
        const bf* __restrict__ Vh, const bf* __restrict__ Vl,
        bf* __restrict__ Oh, bf* __restrict__ Ol,
        int Nq, int Nk)
{
    extern __shared__ char smem[];
    const int QOFF=0, KOFF=36864, VOFF=110592, UOFF=145408, RSC=217088, RLI=217600;
    const int tid = threadIdx.x, lane = tid&31, w = tid>>5;
    const int wm = w&1, wn = w>>1;
    const int gid = lane>>2, t4 = lane&3;
    uint32_t sb = cvsm(smem);

    int z = blockIdx.z, b = z>>3, h = z&7;
    long qrow0 = (long)b*Nq + (long)blockIdx.y*128;
    const bf* qh = Qh + qrow0*KD + h*KDH;
    const bf* ql = Ql + qrow0*KD + h*KDH;
    const bf* kh = Kh + (long)b*Nk*KD + h*KDH;
    const bf* kl = Kl + (long)b*Nk*KD + h*KDH;
    const bf* vh = Vh + ((long)b*KD + h*KDH)*(long)Nk;
    const bf* vl = Vl + ((long)b*KD + h*KDH)*(long)Nk;

    // Q load (once)
    #pragma unroll
    for(int i=0;i<4;i++){
        int wd = tid + (i<<8); int r = wd>>3, wi = wd&7;
        CPA(sb + QOFF + r*144 + wi*16,        qh + (long)r*KD + wi*8);
        CPA(sb + QOFF + 18432 + r*144 + wi*16, ql + (long)r*KD + wi*8);
    }
    CPA_COMMIT();

    int NKB = Nk >> 7;

    // K block load
    auto loadK = [&](int kb){
        uint32_t base = sb + KOFF + (uint32_t)(kb&1)*36864u;
        const bf* sh_ = kh + (long)kb*128*KD;
        const bf* sl_ = kl + (long)kb*128*KD;
        #pragma unroll
        for(int i=0;i<4;i++){
            int wd = tid + (i<<8); int r = wd>>3, wi = wd&7;
            CPA(base + r*144 + wi*16,         sh_ + (long)r*KD + wi*8);
            CPA(base + 18432 + r*144 + wi*16, sl_ + (long)r*KD + wi*8);
        }
        CPA_COMMIT();
    };
    // V block load (64 d-rows x 128 keys)
    auto loadV = [&](int kb){
        #pragma unroll
        for(int i=0;i<4;i++){
            int wd = tid + (i<<8); int r = wd>>4, wi = wd&15;
            CPA(sb + VOFF + r*272 + wi*16,         vh + (long)r*Nk + kb*128 + wi*8);
            CPA(sb + VOFF + 17408 + r*272 + wi*16, vl + (long)r*Nk + kb*128 + wi*8);
        }
        CPA_COMMIT();
    };
    loadK(0); loadV(0);

    float m0 = -1e30f, l0 = 0.f;        // softmax state: row tid>>1, half tid&1
    float occ[8][4];
    #pragma unroll
    for(int j=0;j<8;j++){ occ[j][0]=0.f; occ[j][1]=0.f; occ[j][2]=0.f; occ[j][3]=0.f; }

    for(int kb=0; kb<NKB; kb++){
        CPA_WAIT0();
        __syncthreads();
        uint32_t Kb = sb + KOFF + (uint32_t)(kb&1)*36864u;

        // GEMM1: S = Q·K^T
        float cc[4][4][4];
        #pragma unroll
        for(int i=0;i<4;i++)
            #pragma unroll
            for(int j=0;j<4;j++){ cc[i][j][0]=0.f; cc[i][j][1]=0.f; cc[i][j][2]=0.f; cc[i][j][3]=0.f; }
        #pragma unroll
        for(int kc=0;kc<4;kc++){
            uint32_t bh_[4][2], bl_[4][2];
            #pragma unroll
            for(int jp=0;jp<2;jp++){
                int nr = wn*32 + jp*16 + (lane&7) + (((lane>>4)&1)<<3);
                uint32_t cb = (uint32_t)(((lane>>3)&1)<<4);
                uint32_t ad = Kb + (uint32_t)(nr*144) + (uint32_t)(kc*32) + cb;
                ldm_x4(&bh_[2*jp][0], ad);
                ldm_x4(&bl_[2*jp][0], ad + 18432u);
            }
            #pragma unroll
            for(int mt=0;mt<4;mt++){
                int ar = wm*64 + mt*16 + (lane&15);
                uint32_t cb = (uint32_t)(((lane>>4)&1)<<4);
                uint32_t ad = sb + QOFF + (uint32_t)(ar*144) + (uint32_t)(kc*32) + cb;
                uint32_t ah[4], al[4];
                ldm_x4(ah, ad);
                ldm_x4(al, ad + 18432u);
                #pragma unroll
                for(int j=0;j<4;j++){
                    mma_bf(cc[mt][j], ah, bh_[j]);
                    mma_bf(cc[mt][j], ah, bl_[j]);
                    mma_bf(cc[mt][j], al, bh_[j]);
                }
            }
        }
        // S -> smem (fp32)
        #pragma unroll
        for(int mt=0;mt<4;mt++)
            #pragma unroll
            for(int j=0;j<4;j++){
                int col = wn*32 + j*8 + t4*2;
                int r0 = wm*64 + mt*16 + gid;
                float2 v0; v0.x = cc[mt][j][0]; v0.y = cc[mt][j][1];
                float2 v1; v1.x = cc[mt][j][2]; v1.y = cc[mt][j][3];
                *(float2*)(smem + UOFF + r0*560 + col*4)       = v0;
                *(float2*)(smem + UOFF + (r0+8)*560 + col*4)   = v1;
            }
        // prefetch next K (alt buffer free)
        if(kb+1 < NKB) loadK(kb+1);
        __syncthreads();

        // softmax (row = tid>>1, half = tid&1)
        {
            int row = tid>>1, hf = tid&1;
            const float* sp = (const float*)(smem + UOFF + row*560) + hf*64;
            float sv[64]; float mx = -1e30f;
            #pragma unroll
            for(int i=0;i<64;i++){ sv[i] = sp[i]*0.125f; mx = fmaxf(mx, sv[i]); }
            mx = fmaxf(mx, __shfl_xor_sync(~0u, mx, 1));
            float mnew = fmaxf(m0, mx);
            float sum = 0.f;
            #pragma unroll
            for(int i=0;i<64;i++){ sv[i] = __expf(sv[i]-mnew); sum += sv[i]; }
            sum += __shfl_xor_sync(~0u, sum, 1);
            float scl = __expf(m0 - mnew);
            l0 = l0*scl + sum; m0 = mnew;
            if(hf==0) ((float*)(smem+RSC))[row] = scl;
            bf* pph = (bf*)(smem + UOFF + row*560) + hf*64;
            bf* ppl = (bf*)(smem + UOFF + row*560 + 256) + hf*64;
            #pragma unroll
            for(int i=0;i<64;i++) splitw(sv[i], pph+i, ppl+i);
        }
        __syncthreads();

        // GEMM2: O = O*scale + P·V
        {
            float s0 = ((float*)(smem+RSC))[16*w + gid];
            float s1 = ((float*)(smem+RSC))[16*w + gid + 8];
            #pragma unroll
            for(int j=0;j<8;j++){ occ[j][0]*=s0; occ[j][1]*=s0; occ[j][2]*=s1; occ[j][3]*=s1; }
            #pragma unroll
            for(int ch=0;ch<8;ch++){
                uint32_t pa = sb + UOFF + (uint32_t)((16*w + (lane&15))*560)
                              + (uint32_t)(ch*32) + (uint32_t)(((lane>>4)&1)<<4);
                uint32_t ph_[4], pl_[4];
                ldm_x4(ph_, pa);
                ldm_x4(pl_, pa + 256u);
                uint32_t vbh[8][2], vbl[8][2];
                #pragma unroll
                for(int jp=0;jp<4;jp++){
                    int nr = jp*16 + (lane&7) + (((lane>>4)&1)<<3);
                    uint32_t cb = (uint32_t)(((lane>>3)&1)<<4);
                    uint32_t ad = sb + VOFF + (uint32_t)(nr*272) + (uint32_t)(ch*32) + cb;
                    ldm_x4(&vbh[2*jp][0], ad);
                    ldm_x4(&vbl[2*jp][0], ad + 17408u);
                }
                #pragma unroll
                for(int j=0;j<8;j++){
                    mma_bf(occ[j], ph_, vbh[j]);
                    mma_bf(occ[j], ph_, vbl[j]);
                    mma_bf(occ[j], pl_, vbh[j]);
                }
            }
        }
        __syncthreads();
        if(kb+1 < NKB) loadV(kb+1);
    }

    // epilogue: divide by l, write O hi/lo
    if((tid&1)==0) ((float*)(smem+RLI))[tid>>1] = 1.f/l0;
    __syncthreads();
    float li0 = ((float*)(smem+RLI))[16*w + gid];
    float li1 = ((float*)(smem+RLI))[16*w + gid + 8];
    #pragma unroll
    for(int j=0;j<8;j++){
        int col = h*KDH + j*8 + t4*2;
        long r0 = qrow0 + 16*w + gid;
        long r1 = r0 + 8;
        float a0 = occ[j][0]*li0, a1 = occ[j][1]*li0;
        float a2 = occ[j][2]*li1, a3 = occ[j][3]*li1;
        __nv_bfloat162 hp, lp;
        hp.x = __float2bfloat16(a0); hp.y = __float2bfloat16(a1);
        lp.x = __float2bfloat16(a0 - __bfloat162float(hp.x));
        lp.y = __float2bfloat16(a1 - __bfloat162float(hp.y));
        *(__nv_bfloat162*)(Oh + r0*KD + col) = hp;
        *(__nv_bfloat162*)(Ol + r0*KD + col) = lp;
        hp.x = __float2bfloat16(a2); hp.y = __float2bfloat16(a3);
        lp.x = __float2bfloat16(a2 - __bfloat162float(hp.x));
        lp.y = __float2bfloat16(a3 - __bfloat162float(hp.y));
        *(__nv_bfloat162*)(Oh + r1*KD + col) = hp;
        *(__nv_bfloat162*)(Ol + r1*KD + col) = lp;
    }
}

// ---------------- split-bf16 HMMA GEMM (NT) ----------------
template<int BN>
__global__ void __launch_bounds__(256)
gemm_mma(const bf* __restrict__ Ah, const bf* __restrict__ Al,
         const bf* __restrict__ Bh, const bf* __restrict__ Bl,
         const float* __restrict__ bias, int biasMode, const float* __restrict__ Res,
         float* __restrict__ Cf, bf* __restrict__ Ch, bf* __restrict__ Cl, int doGate,
         int K, int lda, int ldb, int ldc,
         int Hn, long sAb, long sAh2, long sBb, long sBh2, long sCb, long sCh2,
         float alpha)
{
    extern __shared__ char smem[];
    const int tid = threadIdx.x, lane = tid&31, w = tid>>5;
    const int wm = w&1, wn = w>>1;
    const int gid = lane>>2, t4 = lane&3;
    constexpr int NT = BN/32;
    constexpr int BW = BN/64;
    constexpr int SS = 20480 + BN*160;

    int z = blockIdx.z, zb = z/Hn, zh = z - zb*Hn;
    long coff = (long)zb*sCb + (long)zh*sCh2;
    Ah += (long)zb*sAb + (long)zh*sAh2; Al += (long)zb*sAb + (long)zh*sAh2;
    Bh += (long)zb*sBb + (long)zh*sBh2; Bl += (long)zb*sBb + (long)zh*sBh2;

    const int row0 = blockIdx.y << 7;
    const int col0 = blockIdx.x * BN;
    uint32_t sb = cvsm(smem);
    int nch = K >> 5;

    float cc[4][NT][4];
    #pragma unroll
    for(int i=0;i<4;i++)
        #pragma unroll
        for(int j=0;j<NT;j++)
            #pragma unroll
            for(int q=0;q<4;q++) cc[i][j][q]=0.f;

    auto issue = [&](int kc){
        uint32_t bufb = sb + (uint32_t)(kc&1)*SS;
        int k0 = kc<<5;
        #pragma unroll
        for(int i=0;i<2;i++){
            int wd = tid + (i<<8); int r = wd>>2, wi = wd&3;
            uint32_t so = bufb + (uint32_t)(r*80 + wi*16);
            long go = (long)(row0+r)*lda + k0 + (wi<<3);
            CPA(so,         Ah+go);
            CPA(so + 10240, Al+go);
        }
        #pragma unroll
        for(int i=0;i<BW;i++){
            int wd = tid + (i<<8); int r = wd>>2, wi = wd&3;
            uint32_t so = bufb + 20480u + (uint32_t)(r*80 + wi*16);
            long go = (long)(col0+r)*ldb + k0 + (wi<<3);
            CPA(so,           Bh+go);
            CPA(so + BN*80u,  Bl+go);
        }
        CPA_COMMIT();
    };

    issue(0);
    for(int kc=0; kc<nch; kc++){
        if(kc+1 < nch){ issue(kc+1); CPA_WAIT1(); }
        else          { CPA_WAIT0(); }
        __syncthreads();
        uint32_t bufb = sb + (uint32_t)(kc&1)*SS;
        #pragma unroll
        for(int ks=0; ks<2; ks++){
            uint32_t bh[NT][2], bl[NT][2];
            #pragma unroll
            for(int jp=0; jp<NT/2; jp++){
                int nr = wn*(BN/4) + jp*16 + (lane&7) + (((lane>>4)&1)<<3);
                uint32_t cb = (uint32_t)(((lane>>3)&1)<<4);
                uint32_t ad = bufb + 20480u + (uint32_t)(nr*80) + (uint32_t)(ks*32) + cb;
                ldm_x4(&bh[2*jp][0], ad);
                ldm_x4(&bl[2*jp][0], ad + BN*80u);
            }
            #pragma unroll
            for(int mt=0; mt<4; mt++){
                int ar = wm*64 + mt*16 + (lane&15);
                uint32_t cb = (uint32_t)(((lane>>4)&1)<<4);
                uint32_t ad = bufb + (uint32_t)(ar*80) + (uint32_t)(ks*32) + cb;
                uint32_t ah[4], al[4];
                ldm_x4(ah, ad);
                ldm_x4(al, ad + 10240u);
                #pragma unroll
                for(int j=0; j<NT; j++){
                    mma_bf(cc[mt][j], ah, bh[j]);
                    mma_bf(cc[mt][j], ah, bl[j]);
                    mma_bf(cc[mt][j], al, bh[j]);
                }
            }
        }
        __syncthreads();
    }

    #pragma unroll
    for(int mt=0;mt<4;mt++){
        #pragma unroll
        for(int j=0;j<NT;j++){
            int gn = col0 + wn*(BN/4) + j*8 + t4*2;
            #pragma unroll
            for(int h=0;h<2;h++){
                int gm = row0 + wm*64 + mt*16 + gid + 8*h;
                float v0 = cc[mt][j][2*h+0]*alpha;
                float v1 = cc[mt][j][2*h+1]*alpha;
                if(biasMode==1){ v0 += bias[gn]; v1 += bias[gn+1]; }
                else if(biasMode==2){ float bb = bias[gm]; v0 += bb; v1 += bb; }
                if(doGate){
                    float g = (v0/(1.f+__expf(-v0)))*v1;
                    long cr = (long)gm*ldc + (gn>>1);
                    splitw(g, Ch+cr, Cl+cr);
                } else {
                    long cr = (long)gm*ldc + coff + gn;
                    if(Res){ float2 rr = *(const float2*)(Res+cr); v0 += rr.x; v1 += rr.y; }
                    if(Cf){ float2 o; o.x=v0; o.y=v1; *(float2*)(Cf+cr) = o; }
                    if(Ch){
                        __nv_bfloat162 hp, lp;
                        hp.x = __float2bfloat16(v0); hp.y = __float2bfloat16(v1);
                        lp.x = __float2bfloat16(v0 - __bfloat162float(hp.x));
                        lp.y = __float2bfloat16(v1 - __bfloat162float(hp.y));
                        *(__nv_bfloat162*)(Ch+cr) = hp;
                        *(__nv_bfloat162*)(Cl+cr) = lp;
                    }
                }
            }
        }
    }
}

// ---------------- host ----------------
static void ltc(const bf* Ah, const bf* Al, const bf* Bh, const bf* Bl,
                const float* bias, int bMode, const float* Res,
                float* Cf, bf* Ch, bf* Cl, int doGate,
                int M, int N, int K, int lda, int ldb, int ldc,
                int Z, int Hn, long sAb, long sAh, long sBb, long sBh, long sCb, long sCh,
                float alpha)
{
    int smem = 2*(20480 + 128*160);   // 81920
    cudaFuncSetAttribute(gemm_mma<128>, cudaFuncAttributeMaxDynamicSharedMemorySize, smem);
    dim3 g(N/128, M/128, Z);
    gemm_mma<128><<<g, 256, smem>>>(Ah,Al,Bh,Bl,bias,bMode,Res,Cf,Ch,Cl,doGate,
                                    K,lda,ldb,ldc,Hn,sAb,sAh,sBb,sBh,sCb,sCh,alpha);
}
#define SYM(T,v,s) T* v; { void* p_; cudaGetSymbolAddress(&p_, s); v = (T*)p_; }

extern "C" void kernel_launch(void* const* d_in, const int* in_sizes, int n_in,
                              void* d_out, int out_size)
{
    (void)in_sizes; (void)n_in; (void)out_size;
    const float* spatial   = (const float*)d_in[0];
    const float* temporal  = (const float*)d_in[1];
    const float* sLqg=(const float*)d_in[2],  *sLqb=(const float*)d_in[3];
    const float* sLkg=(const float*)d_in[4],  *sLkb=(const float*)d_in[5];
    const float* sWqkv=(const float*)d_in[6], *sBqkv=(const float*)d_in[7];
    const float* sWo=(const float*)d_in[8],   *sBo=(const float*)d_in[9];
    const float* sWp=(const float*)d_in[10],  *sBp=(const float*)d_in[11];
    const float* tLqg=(const float*)d_in[12], *tLqb=(const float*)d_in[13];
    const float* tLkg=(const float*)d_in[14], *tLkb=(const float*)d_in[15];
    const float* tWqkv=(const float*)d_in[16],*tBqkv=(const float*)d_in[17];
    const float* tWo=(const float*)d_in[18],  *tBo=(const float*)d_in[19];
    const float* tWp=(const float*)d_in[20],  *tBp=(const float*)d_in[21];
    const float* mLg=(const float*)d_in[22],  *mLb=(const float*)d_in[23];
    const float* mWin=(const float*)d_in[24], *mBin=(const float*)d_in[25];
    const float* mWout=(const float*)d_in[26],*mBout=(const float*)d_in[27];
    float* out = (float*)d_out;

    SYM(bf,lsqh,LsQh) SYM(bf,lsql,LsQl) SYM(bf,ltkh,LtKVh) SYM(bf,ltkl,LtKVl)
    SYM(bf,ltqh,LtQh) SYM(bf,ltql,LtQl) SYM(bf,lskh,LsKVh) SYM(bf,lskl,LsKVl)
    SYM(bf,qsh,Qsh) SYM(bf,qsl,Qsl) SYM(bf,ksh,Ksh) SYM(bf,ksl,Ksl)
    SYM(bf,vsh,VtSh) SYM(bf,vsl,VtSl) SYM(bf,qth,Qth) SYM(bf,qtl,Qtl)
    SYM(bf,kth,Kth) SYM(bf,ktl,Ktl) SYM(bf,vth,VtTh) SYM(bf,vtl,VtTl)
    SYM(bf,ash,AtSh) SYM(bf,asl,AtSl) SYM(bf,ath,AtTh) SYM(bf,atl,AtTl)
    SYM(bf,h1sh,H1Sh) SYM(bf,h1sl,H1Sl) SYM(bf,h1th,H1Th) SYM(bf,h1tl,H1Tl)
    SYM(float,sctx,SctxF) SYM(float,tctx,TctxF) SYM(float,tmn,TmeanF)
    SYM(bf,hmh,Hmh) SYM(bf,hml,Hml)
    SYM(bf,gth,Gth) SYM(bf,gtl,Gtl)
    SYM(bf,wqsh,WqkvSh) SYM(bf,wqsl,WqkvSl) SYM(bf,wqth,WqkvTh) SYM(bf,wqtl,WqkvTl)
    SYM(bf,wosh,WoSh) SYM(bf,wosl,WoSl) SYM(bf,wpsh,WpSh) SYM(bf,wpsl,WpSl)
    SYM(bf,woth,WoTh) SYM(bf,wotl,WoTl) SYM(bf,wpth,WpTh) SYM(bf,wptl,WpTl)
    SYM(bf,winh,Winh) SYM(bf,winl,Winl) SYM(bf,wouth,Wouth) SYM(bf,woutl,Woutl)
    SYM(float,binp,BinP)

    #define CV(src,dh,dl,dR,dC,sR,sC) conv_k<<<(int)(((long)(dR)*(dC)+255)/256),256>>>(src,dh,dl,dR,dC,sR,sC)
    CV(sWqkv,wqsh,wqsl,3*KD,KD,3*KD,KD);
    CV(tWqkv,wqth,wqtl,3*KD,KD,3*KD,KD);
    CV(sWo,wosh,wosl,KD,KD,KD,KD);   CV(sWp,wpsh,wpsl,KD,KD,KD,KD);
    CV(tWo,woth,wotl,KD,KD,KD,KD);   CV(tWp,wpth,wptl,KD,KD,KD,KD);
    convin_k<<<(int)(((long)NPAD*2*KD+255)/256),256>>>(mWin, winh, winl);
    CV(mWout,wouth,woutl,KD,KPAD,KD,KHID);
    padbin_k<<<(NPAD+255)/256,256>>>(mBin, binp);

    ln_k<<<SROWS,128>>>(spatial, sLqg,sLqb, lsqh,lsql);
    ln_k<<<TROWS,128>>>(temporal,sLkg,sLkb, ltkh,ltkl);
    ln_k<<<TROWS,128>>>(temporal,tLqg,tLqb, ltqh,ltql);
    ln_k<<<SROWS,128>>>(spatial, tLkg,tLkb, lskh,lskl);

    // projections
    ltc(lsqh,lsql, wqsh,wqsl, sBqkv,1,0, 0,qsh,qsl,0, SROWS,KD,KD, KD,KD,KD, 1,1,0,0,0,0,0,0, 1.f);
    ltc(ltkh,ltkl, wqsh+KD*KD,wqsl+KD*KD, sBqkv+KD,1,0, 0,ksh,ksl,0, TROWS,KD,KD, KD,KD,KD, 1,1,0,0,0,0,0,0, 1.f);
    ltc(wqsh+2*KD*KD,wqsl+2*KD*KD, ltkh,ltkl, sBqkv+2*KD,2,0, 0,vsh,vsl,0, KD,KNT,KD, KD,KD,KNT,
        KB,1, 0,0, (long)KNT*KD,0, (long)KD*KNT,0, 1.f);
    ltc(ltqh,ltql, wqth,wqtl, tBqkv,1,0, 0,qth,qtl,0, TROWS,KD,KD, KD,KD,KD, 1,1,0,0,0,0,0,0, 1.f);
    ltc(lskh,lskl, wqth+KD*KD,wqtl+KD*KD, tBqkv+KD,1,0, 0,kth,ktl,0, SROWS,KD,KD, KD,KD,KD, 1,1,0,0,0,0,0,0, 1.f);
    ltc(wqth+2*KD*KD,wqtl+2*KD*KD, lskh,lskl, tBqkv+2*KD,2,0, 0,vth,vtl,0, KD,KNS,KD, KD,KD,KNS,
        KB,1, 0,0, (long)KNS*KD,0, (long)KD*KNS,0, 1.f);

    // fused attention
    {
        int fsm = 218112;
        cudaFuncSetAttribute(flash_k, cudaFuncAttributeMaxDynamicSharedMemorySize, fsm);
        dim3 gs(1, KNS/128, KB*KH);
        flash_k<<<gs, 256, fsm>>>(qsh,qsl, ksh,ksl, vsh,vsl, ash,asl, KNS, KNT);
        dim3 gt(1, KNT/128, KB*KH);
        flash_k<<<gt, 256, fsm>>>(qth,qtl, kth,ktl, vth,vtl, ath,atl, KNT, KNS);
    }

    ltc(ash,asl, wosh,wosl, sBo,1,0, 0,h1sh,h1sl,0, SROWS,KD,KD, KD,KD,KD, 1,1,0,0,0,0,0,0, 1.f);
    ltc(h1sh,h1sl, wpsh,wpsl, sBp,1,spatial, sctx,0,0,0, SROWS,KD,KD, KD,KD,KD, 1,1,0,0,0,0,0,0, 1.f);
    ltc(ath,atl, woth,wotl, tBo,1,0, 0,h1th,h1tl,0, TROWS,KD,KD, KD,KD,KD, 1,1,0,0,0,0,0,0, 1.f);
    ltc(h1th,h1tl, wpth,wptl, tBp,1,temporal, tctx,0,0,0, TROWS,KD,KD, KD,KD,KD, 1,1,0,0,0,0,0,0, 1.f);

    // mix
    tmean_k<<<(KB*KD+127)/128,128>>>(tctx, tmn);
    mixln_k<<<SROWS,128>>>(sctx, tmn, mLg, mLb, hmh, hml);
    ltc(hmh,hml, winh,winl, binp,1,0, 0,gth,gtl,1, SROWS,NPAD,2*KD, 2*KD,2*KD,KPAD, 1,1,0,0,0,0,0,0, 1.f);
    ltc(gth,gtl, wouth,woutl, mBout,1,sctx, out,0,0,0, SROWS,KD,KPAD, KPAD,KPAD,KD, 1,1,0,0,0,0,0,0, 1.f);
}